// round 11
// baseline (speedup 1.0000x reference)
#include <cuda_runtime.h>

#define BB 2
#define CC 3
#define DD 128
#define HH 128
#define WW 128
#define HPAIR (HH / 2)
#define NTASKS (BB * DD * HPAIR)     // 16384 two-row tasks
#define NTHREADS 128
#define WPB (NTHREADS / 32)
#define NBLOCKS (148 * 6)            // persistent, 6 blocks/SM (<=85 regs)
#define TOTW (NBLOCKS * WPB)         // 3552 warps

#define W_GRAD 0.1f
#define W_TV 0.002f
#define W_BG 0.15

// 10 partial sums:
// 0:mask 1:mx 2:my 3:mz 4:(mae+mse) 5:|p| 6:|p|*m 7:gtx 8:gty 9:gtz
#define NSUMS 10
__device__ double g_sums[NSUMS];
__device__ unsigned int g_count;

__device__ __forceinline__ float warp_sum(float v) {
#pragma unroll
    for (int o = 16; o; o >>= 1) v += __shfl_down_sync(0xffffffffu, v, o);
    return v;
}

__global__ __launch_bounds__(NTHREADS, 6)
void loss_kernel(const float4* __restrict__ pred,
                 const float4* __restrict__ targ,
                 const float4* __restrict__ mask,
                 float* __restrict__ out) {
    const int wid   = threadIdx.x >> 5;
    const int lane  = threadIdx.x & 31;
    const int gwarp = blockIdx.x * WPB + wid;

    const float ze = (lane < 31) ? 1.0f : 0.0f;       // w=127 edge
    const int ROWQ = WW / 4;                          // 32 float4 per row
    const int CSTR = DD * HH * ROWQ;                  // channel stride

    float s_m = 0.f, s_mx = 0.f, s_my = 0.f, s_mz = 0.f;
    float s_mm = 0.f, s_ba = 0.f, s_bm = 0.f;
    float s_gtx = 0.f, s_gty = 0.f, s_gtz = 0.f;

    // Grid-stride over (b, d, h-pair) tasks: rows h0 and h0+1 fused so
    // row1's self-load doubles as row0's h-neighbor. Interleaved order
    // keeps d+1 / h+2 reloads L2-resident (neighbor tasks concurrent).
    // Clamped neighbors self-zero the grad/TV terms; validity factors
    // are applied only to the mask counts.
    for (int task = gwarp; task < NTASKS; task += TOTW) {
        const int h0 = (task & (HPAIR - 1)) * 2;
        const int bd = task >> 6;                     // b*DD + d
        const int d  = bd & (DD - 1);
        const int b  = bd >> 7;

        const int dskip = (d < DD - 1) ? HH * ROWQ : 0;
        const int hs1   = (h0 < HH - 2) ? ROWQ : 0;   // row1's h-neighbor

        const int mo = (bd * HH + h0) * ROWQ + lane;
        const int po = mo + b * (CC - 1) * CSTR;

        const float4 M0  = mask[mo];
        const float4 M1  = mask[mo + ROWQ];
        const float4 M2  = mask[mo + ROWQ + hs1];
        const float4 MD0 = mask[mo + dskip];
        const float4 MD1 = mask[mo + ROWQ + dskip];

        const float4 mx0 = make_float4(fminf(M0.x, MD0.x), fminf(M0.y, MD0.y),
                                       fminf(M0.z, MD0.z), fminf(M0.w, MD0.w));
        const float4 mx1 = make_float4(fminf(M1.x, MD1.x), fminf(M1.y, MD1.y),
                                       fminf(M1.z, MD1.z), fminf(M1.w, MD1.w));
        const float4 my0 = make_float4(fminf(M0.x, M1.x), fminf(M0.y, M1.y),
                                       fminf(M0.z, M1.z), fminf(M0.w, M1.w));
        const float4 my1 = make_float4(fminf(M1.x, M2.x), fminf(M1.y, M2.y),
                                       fminf(M1.z, M2.z), fminf(M1.w, M2.w));

        const float mnx0 = __shfl_down_sync(0xffffffffu, M0.x, 1);
        const float mnx1 = __shfl_down_sync(0xffffffffu, M1.x, 1);
        const float za0 = fminf(M0.x, M0.y), zb0 = fminf(M0.y, M0.z);
        const float zc0 = fminf(M0.z, M0.w), zd0 = fminf(M0.w, mnx0) * ze;
        const float za1 = fminf(M1.x, M1.y), zb1 = fminf(M1.y, M1.z);
        const float zc1 = fminf(M1.z, M1.w), zd1 = fminf(M1.w, mnx1) * ze;

        {
            const float dv = (d < DD - 1) ? 1.0f : 0.0f;
            const float hv = (h0 < HH - 2) ? 1.0f : 0.0f;
            s_m  += (M0.x + M0.y) + (M0.z + M0.w)
                  + (M1.x + M1.y) + (M1.z + M1.w);
            s_mx += dv * ((mx0.x + mx0.y) + (mx0.z + mx0.w)
                        + (mx1.x + mx1.y) + (mx1.z + mx1.w));
            s_my += ((my0.x + my0.y) + (my0.z + my0.w))      // always valid
                  + hv * ((my1.x + my1.y) + (my1.z + my1.w));
            s_mz += (za0 + zb0) + (zc0 + zd0) + (za1 + zb1) + (zc1 + zd1);
        }

#pragma unroll
        for (int c = 0; c < CC; c++) {
            const int pc = po + c * CSTR;
            const float4 P0  = pred[pc];
            const float4 T0  = targ[pc];
            const float4 P1  = pred[pc + ROWQ];
            const float4 T1  = targ[pc + ROWQ];
            const float4 P2  = pred[pc + ROWQ + hs1];
            const float4 T2  = targ[pc + ROWQ + hs1];
            const float4 PD0 = pred[pc + dskip];
            const float4 TD0 = targ[pc + dskip];
            const float4 PD1 = pred[pc + ROWQ + dskip];
            const float4 TD1 = targ[pc + ROWQ + dskip];

            const float4 df0  = make_float4(P0.x - T0.x, P0.y - T0.y,
                                            P0.z - T0.z, P0.w - T0.w);
            const float4 df1  = make_float4(P1.x - T1.x, P1.y - T1.y,
                                            P1.z - T1.z, P1.w - T1.w);
            const float4 df2  = make_float4(P2.x - T2.x, P2.y - T2.y,
                                            P2.z - T2.z, P2.w - T2.w);
            const float4 dfd0 = make_float4(PD0.x - TD0.x, PD0.y - TD0.y,
                                            PD0.z - TD0.z, PD0.w - TD0.w);
            const float4 dfd1 = make_float4(PD1.x - TD1.x, PD1.y - TD1.y,
                                            PD1.z - TD1.z, PD1.w - TD1.w);

            // (|diff| + diff^2) * m for both rows
            s_mm += fmaf(df0.x, df0.x, fabsf(df0.x)) * M0.x
                  + fmaf(df0.y, df0.y, fabsf(df0.y)) * M0.y
                  + fmaf(df0.z, df0.z, fabsf(df0.z)) * M0.z
                  + fmaf(df0.w, df0.w, fabsf(df0.w)) * M0.w
                  + fmaf(df1.x, df1.x, fabsf(df1.x)) * M1.x
                  + fmaf(df1.y, df1.y, fabsf(df1.y)) * M1.y
                  + fmaf(df1.z, df1.z, fabsf(df1.z)) * M1.z
                  + fmaf(df1.w, df1.w, fabsf(df1.w)) * M1.w;
            // |p|*(1-m) = sum|p| - sum|p|*m
            s_ba += (fabsf(P0.x) + fabsf(P0.y)) + (fabsf(P0.z) + fabsf(P0.w))
                  + (fabsf(P1.x) + fabsf(P1.y)) + (fabsf(P1.z) + fabsf(P1.w));
            s_bm += fabsf(P0.x) * M0.x + fabsf(P0.y) * M0.y
                  + fabsf(P0.z) * M0.z + fabsf(P0.w) * M0.w
                  + fabsf(P1.x) * M1.x + fabsf(P1.y) * M1.y
                  + fabsf(P1.z) * M1.z + fabsf(P1.w) * M1.w;

            // x-direction (d): rows 0 and 1
            s_gtx += fmaf(W_TV, fabsf(PD0.x - P0.x), W_GRAD * fabsf(dfd0.x - df0.x)) * mx0.x
                   + fmaf(W_TV, fabsf(PD0.y - P0.y), W_GRAD * fabsf(dfd0.y - df0.y)) * mx0.y
                   + fmaf(W_TV, fabsf(PD0.z - P0.z), W_GRAD * fabsf(dfd0.z - df0.z)) * mx0.z
                   + fmaf(W_TV, fabsf(PD0.w - P0.w), W_GRAD * fabsf(dfd0.w - df0.w)) * mx0.w
                   + fmaf(W_TV, fabsf(PD1.x - P1.x), W_GRAD * fabsf(dfd1.x - df1.x)) * mx1.x
                   + fmaf(W_TV, fabsf(PD1.y - P1.y), W_GRAD * fabsf(dfd1.y - df1.y)) * mx1.y
                   + fmaf(W_TV, fabsf(PD1.z - P1.z), W_GRAD * fabsf(dfd1.z - df1.z)) * mx1.z
                   + fmaf(W_TV, fabsf(PD1.w - P1.w), W_GRAD * fabsf(dfd1.w - df1.w)) * mx1.w;

            // y-direction (h): row0 uses row1 (shared), row1 uses row2
            s_gty += fmaf(W_TV, fabsf(P1.x - P0.x), W_GRAD * fabsf(df1.x - df0.x)) * my0.x
                   + fmaf(W_TV, fabsf(P1.y - P0.y), W_GRAD * fabsf(df1.y - df0.y)) * my0.y
                   + fmaf(W_TV, fabsf(P1.z - P0.z), W_GRAD * fabsf(df1.z - df0.z)) * my0.z
                   + fmaf(W_TV, fabsf(P1.w - P0.w), W_GRAD * fabsf(df1.w - df0.w)) * my0.w
                   + fmaf(W_TV, fabsf(P2.x - P1.x), W_GRAD * fabsf(df2.x - df1.x)) * my1.x
                   + fmaf(W_TV, fabsf(P2.y - P1.y), W_GRAD * fabsf(df2.y - df1.y)) * my1.y
                   + fmaf(W_TV, fabsf(P2.z - P1.z), W_GRAD * fabsf(df2.z - df1.z)) * my1.z
                   + fmaf(W_TV, fabsf(P2.w - P1.w), W_GRAD * fabsf(df2.w - df1.w)) * my1.w;

            // z-direction (w, cross-lane): rows 0 and 1
            const float dn0 = __shfl_down_sync(0xffffffffu, df0.x, 1);
            const float pn0 = __shfl_down_sync(0xffffffffu, P0.x, 1);
            const float dn1 = __shfl_down_sync(0xffffffffu, df1.x, 1);
            const float pn1 = __shfl_down_sync(0xffffffffu, P1.x, 1);
            s_gtz += fmaf(W_TV, fabsf(P0.y - P0.x), W_GRAD * fabsf(df0.y - df0.x)) * za0
                   + fmaf(W_TV, fabsf(P0.z - P0.y), W_GRAD * fabsf(df0.z - df0.y)) * zb0
                   + fmaf(W_TV, fabsf(P0.w - P0.z), W_GRAD * fabsf(df0.w - df0.z)) * zc0
                   + fmaf(W_TV, fabsf(pn0 - P0.w),  W_GRAD * fabsf(dn0 - df0.w))  * zd0
                   + fmaf(W_TV, fabsf(P1.y - P1.x), W_GRAD * fabsf(df1.y - df1.x)) * za1
                   + fmaf(W_TV, fabsf(P1.z - P1.y), W_GRAD * fabsf(df1.z - df1.y)) * zb1
                   + fmaf(W_TV, fabsf(P1.w - P1.z), W_GRAD * fabsf(df1.w - df1.z)) * zc1
                   + fmaf(W_TV, fabsf(pn1 - P1.w),  W_GRAD * fabsf(dn1 - df1.w))  * zd1;
        }
    }

    // ---- block-level reduction: warp -> smem -> NSUMS atomics per block ----
    __shared__ float red[WPB][NSUMS];
    float vals[NSUMS] = {s_m, s_mx, s_my, s_mz, s_mm, s_ba, s_bm,
                         s_gtx, s_gty, s_gtz};
#pragma unroll
    for (int i = 0; i < NSUMS; i++) {
        const float r = warp_sum(vals[i]);
        if (lane == 0) red[wid][i] = r;
    }
    __syncthreads();

    if (threadIdx.x < NSUMS) {
        float acc = red[0][threadIdx.x];
#pragma unroll
        for (int w = 1; w < WPB; w++) acc += red[w][threadIdx.x];
        atomicAdd(&g_sums[threadIdx.x], (double)acc);
        __threadfence();
    }
    __syncthreads();

    // ---- last block finalizes + resets scratch (graph-replay determinism) ----
    if (threadIdx.x == 0) {
        const unsigned int old = atomicAdd(&g_count, 1u);
        if (old == NBLOCKS - 1) {
            double s[NSUMS];
#pragma unroll
            for (int i = 0; i < NSUMS; i++) s[i] = atomicAdd(&g_sums[i], 0.0);
            const double e = 1e-8;
            const double sm  = s[0], smx = s[1], smy = s[2], smz = s[3];
            const double mm  = s[4];
            const double bg  = s[5] - s[6];     // sum|p| - sum|p|*m
            const double gtx = s[7], gty = s[8], gtz = s[9];
            const double inv = (double)BB * DD * HH * WW - sm;

            const double r = mm / (sm * 3.0 + e)          // mae + mse
                           + gtx / (smx * 3.0 + e)
                           + gty / (smy * 3.0 + e)
                           + gtz / (smz * 3.0 + e)
                           + W_BG * (bg / (inv * 3.0 + e));
            out[0] = (float)r;

#pragma unroll
            for (int i = 0; i < NSUMS; i++) g_sums[i] = 0.0;
            g_count = 0u;
        }
    }
}

extern "C" void kernel_launch(void* const* d_in, const int* in_sizes, int n_in,
                              void* d_out, int out_size) {
    // mask is the smallest input; pred/target keep their relative order
    int mi = 0;
    for (int i = 1; i < n_in; i++)
        if (in_sizes[i] < in_sizes[mi]) mi = i;
    int others[2], k = 0;
    for (int i = 0; i < 3; i++)
        if (i != mi) others[k++] = i;

    const float4* pred = (const float4*)d_in[others[0]];
    const float4* targ = (const float4*)d_in[others[1]];
    const float4* mask = (const float4*)d_in[mi];

    loss_kernel<<<NBLOCKS, NTHREADS>>>(pred, targ, mask, (float*)d_out);
}

// round 12
// speedup vs baseline: 1.1720x; 1.1720x over previous
#include <cuda_runtime.h>

#define BB 2
#define CC 3
#define DD 128
#define HH 128
#define WW 128
#define NTASKS (BB * DD * HH)        // 32768 row tasks (b,d,h)
#define NTHREADS 128
#define WPB (NTHREADS / 32)
#define NBLOCKS (148 * 8)            // persistent: 8 blocks/SM, 32 warps/SM
#define TOTW (NBLOCKS * WPB)

#define W_GRAD 0.1f
#define W_TV 0.002f
#define W_BG 0.15

// 9 partial sums: 0:m 1:mx 2:my 3:mz 4:(mae+mse) 5:bg 6:gtx 7:gty 8:gtz
#define NSUMS 9
__device__ double g_sums[NSUMS];
__device__ unsigned int g_count;

__device__ __forceinline__ float warp_sum(float v) {
#pragma unroll
    for (int o = 16; o; o >>= 1) v += __shfl_down_sync(0xffffffffu, v, o);
    return v;
}

__global__ __launch_bounds__(NTHREADS, 8)   // 64-reg cap: R7 body, +4 warps/SM
void loss_kernel(const float4* __restrict__ pred,
                 const float4* __restrict__ targ,
                 const float4* __restrict__ mask,
                 float* __restrict__ out) {
    const int wid   = threadIdx.x >> 5;
    const int lane  = threadIdx.x & 31;
    const int gwarp = blockIdx.x * WPB + wid;

    const float ze = (lane < 31) ? 1.0f : 0.0f;       // w=127 edge
    const int ROWQ = WW / 4;                          // 32 float4 per row
    const int CSTR = DD * HH * ROWQ;                  // channel stride (float4)

    float s_m = 0.f, s_mx = 0.f, s_my = 0.f, s_mz = 0.f;
    float s_mm = 0.f, s_bg = 0.f;
    float s_gtx = 0.f, s_gty = 0.f, s_gtz = 0.f;

    // Persistent grid-stride over independent (b,d,h) row tasks.
    // Interleaved order => h+1 / d+1 reloads are L1/L2 hits (neighbor
    // tasks run concurrently). Clamped neighbors self-zero the grad/TV
    // terms, so validity factors apply only to the mask counts.
    for (int task = gwarp; task < NTASKS; task += TOTW) {
        const int h = task & (HH - 1);
        const int d = (task >> 7) & (DD - 1);
        const int b = task >> 14;

        const int dskip = (d < DD - 1) ? HH * ROWQ : 0;
        const int hskip = (h < HH - 1) ? ROWQ : 0;

        const int mo = task * ROWQ + lane;
        const int po = mo + b * (CC - 1) * CSTR;

        const float4 m  = mask[mo];
        const float4 md = mask[mo + dskip];
        const float4 mh = mask[mo + hskip];

        const float4 mx4 = make_float4(fminf(m.x, md.x), fminf(m.y, md.y),
                                       fminf(m.z, md.z), fminf(m.w, md.w));
        const float4 my4 = make_float4(fminf(m.x, mh.x), fminf(m.y, mh.y),
                                       fminf(m.z, mh.z), fminf(m.w, mh.w));
        const float mnx = __shfl_down_sync(0xffffffffu, m.x, 1);
        const float mz0 = fminf(m.x, m.y), mz1 = fminf(m.y, m.z);
        const float mz2 = fminf(m.z, m.w), mz3 = fminf(m.w, mnx) * ze;

        {   // mask counts (validity factors only here; terms self-zero)
            const float dv = (d < DD - 1) ? 1.0f : 0.0f;
            const float hv = (h < HH - 1) ? 1.0f : 0.0f;
            s_m  += (m.x + m.y) + (m.z + m.w);
            s_mx += dv * ((mx4.x + mx4.y) + (mx4.z + mx4.w));
            s_my += hv * ((my4.x + my4.y) + (my4.z + my4.w));
            s_mz += (mz0 + mz1) + (mz2 + mz3);
        }

        // 1 - m, computed once, reused by all 3 channels
        const float4 inm = make_float4(1.f - m.x, 1.f - m.y,
                                       1.f - m.z, 1.f - m.w);

#pragma unroll
        for (int c = 0; c < CC; c++) {
            const float4 p  = pred[po + c * CSTR];
            const float4 t  = targ[po + c * CSTR];
            const float4 pd = pred[po + c * CSTR + dskip];
            const float4 td = targ[po + c * CSTR + dskip];
            const float4 ph = pred[po + c * CSTR + hskip];
            const float4 th = targ[po + c * CSTR + hskip];

            const float4 df  = make_float4(p.x - t.x, p.y - t.y,
                                           p.z - t.z, p.w - t.w);
            const float4 dfd = make_float4(pd.x - td.x, pd.y - td.y,
                                           pd.z - td.z, pd.w - td.w);
            const float4 dfh = make_float4(ph.x - th.x, ph.y - th.y,
                                           ph.z - th.z, ph.w - th.w);

            // (|diff| + diff^2) * m   (mae+mse share denominator)
            s_mm += fmaf(df.x, df.x, fabsf(df.x)) * m.x
                  + fmaf(df.y, df.y, fabsf(df.y)) * m.y
                  + fmaf(df.z, df.z, fabsf(df.z)) * m.z
                  + fmaf(df.w, df.w, fabsf(df.w)) * m.w;
            // |p| * (1 - m)
            s_bg += fabsf(p.x) * inm.x + fabsf(p.y) * inm.y
                  + fabsf(p.z) * inm.z + fabsf(p.w) * inm.w;

            // grad (0.1) + tv (0.002): shared denominators, weights folded
            s_gtx += fmaf(W_TV, fabsf(pd.x - p.x), W_GRAD * fabsf(dfd.x - df.x)) * mx4.x
                   + fmaf(W_TV, fabsf(pd.y - p.y), W_GRAD * fabsf(dfd.y - df.y)) * mx4.y
                   + fmaf(W_TV, fabsf(pd.z - p.z), W_GRAD * fabsf(dfd.z - df.z)) * mx4.z
                   + fmaf(W_TV, fabsf(pd.w - p.w), W_GRAD * fabsf(dfd.w - df.w)) * mx4.w;

            s_gty += fmaf(W_TV, fabsf(ph.x - p.x), W_GRAD * fabsf(dfh.x - df.x)) * my4.x
                   + fmaf(W_TV, fabsf(ph.y - p.y), W_GRAD * fabsf(dfh.y - df.y)) * my4.y
                   + fmaf(W_TV, fabsf(ph.z - p.z), W_GRAD * fabsf(dfh.z - df.z)) * my4.z
                   + fmaf(W_TV, fabsf(ph.w - p.w), W_GRAD * fabsf(dfh.w - df.w)) * my4.w;

            const float dnx = __shfl_down_sync(0xffffffffu, df.x, 1);
            const float pnx = __shfl_down_sync(0xffffffffu, p.x, 1);
            s_gtz += fmaf(W_TV, fabsf(p.y - p.x), W_GRAD * fabsf(df.y - df.x)) * mz0
                   + fmaf(W_TV, fabsf(p.z - p.y), W_GRAD * fabsf(df.z - df.y)) * mz1
                   + fmaf(W_TV, fabsf(p.w - p.z), W_GRAD * fabsf(df.w - df.z)) * mz2
                   + fmaf(W_TV, fabsf(pnx - p.w), W_GRAD * fabsf(dnx - df.w)) * mz3;
        }
    }

    // ---- block-level reduction: warp -> smem -> NSUMS atomics per block ----
    __shared__ float red[WPB][NSUMS];
    float vals[NSUMS] = {s_m, s_mx, s_my, s_mz, s_mm, s_bg,
                         s_gtx, s_gty, s_gtz};
#pragma unroll
    for (int i = 0; i < NSUMS; i++) {
        const float r = warp_sum(vals[i]);
        if (lane == 0) red[wid][i] = r;
    }
    __syncthreads();

    if (threadIdx.x < NSUMS) {
        float acc = red[0][threadIdx.x];
#pragma unroll
        for (int w = 1; w < WPB; w++) acc += red[w][threadIdx.x];
        atomicAdd(&g_sums[threadIdx.x], (double)acc);
        __threadfence();
    }
    __syncthreads();

    // ---- last block finalizes + resets scratch (graph-replay determinism) ----
    if (threadIdx.x == 0) {
        const unsigned int old = atomicAdd(&g_count, 1u);
        if (old == NBLOCKS - 1) {
            double s[NSUMS];
#pragma unroll
            for (int i = 0; i < NSUMS; i++) s[i] = atomicAdd(&g_sums[i], 0.0);
            const double e = 1e-8;
            const double sm  = s[0], smx = s[1], smy = s[2], smz = s[3];
            const double mm  = s[4], bg  = s[5];
            const double gtx = s[6], gty = s[7], gtz = s[8];
            const double inv = (double)BB * DD * HH * WW - sm;

            const double r = mm / (sm * 3.0 + e)          // mae + mse
                           + gtx / (smx * 3.0 + e)
                           + gty / (smy * 3.0 + e)
                           + gtz / (smz * 3.0 + e)
                           + W_BG * (bg / (inv * 3.0 + e));
            out[0] = (float)r;

#pragma unroll
            for (int i = 0; i < NSUMS; i++) g_sums[i] = 0.0;
            g_count = 0u;
        }
    }
}

extern "C" void kernel_launch(void* const* d_in, const int* in_sizes, int n_in,
                              void* d_out, int out_size) {
    // mask is the smallest input; pred/target keep their relative order
    int mi = 0;
    for (int i = 1; i < n_in; i++)
        if (in_sizes[i] < in_sizes[mi]) mi = i;
    int others[2], k = 0;
    for (int i = 0; i < 3; i++)
        if (i != mi) others[k++] = i;

    const float4* pred = (const float4*)d_in[others[0]];
    const float4* targ = (const float4*)d_in[others[1]];
    const float4* mask = (const float4*)d_in[mi];

    loss_kernel<<<NBLOCKS, NTHREADS>>>(pred, targ, mask, (float*)d_out);
}

// round 13
// speedup vs baseline: 1.3374x; 1.1411x over previous
#include <cuda_runtime.h>

#define BB 2
#define CC 3
#define DD 128
#define HH 128
#define WW 128
#define NTASKS (BB * DD * HH)        // 32768 row tasks (b,d,h)
#define NTHREADS 128
#define WPB (NTHREADS / 32)
#define NBLOCKS (148 * 7)            // persistent: 7 blocks/SM (proven point)
#define TOTW (NBLOCKS * WPB)

#define W_GRAD 0.1f
#define W_TV 0.002f
#define W_BG 0.15

// 9 partial sums: 0:m 1:mx 2:my 3:mz 4:(mae+mse) 5:bg 6:gtx 7:gty 8:gtz
#define NSUMS 9
__device__ double g_sums[NSUMS];
__device__ unsigned int g_count;

__device__ __forceinline__ float warp_sum(float v) {
#pragma unroll
    for (int o = 16; o; o >>= 1) v += __shfl_down_sync(0xffffffffu, v, o);
    return v;
}

__global__ __launch_bounds__(NTHREADS, 7)   // ~72-reg natural fit, no spills
void loss_kernel(const float4* __restrict__ pred,
                 const float4* __restrict__ targ,
                 const float4* __restrict__ mask,
                 float* __restrict__ out) {
    const int wid   = threadIdx.x >> 5;
    const int lane  = threadIdx.x & 31;
    const int gwarp = blockIdx.x * WPB + wid;

    const float ze = (lane < 31) ? 1.0f : 0.0f;       // w=127 edge
    const int ROWQ = WW / 4;                          // 32 float4 per row
    const int CSTR = DD * HH * ROWQ;                  // channel stride (float4)

    float s_m = 0.f, s_mx = 0.f, s_my = 0.f, s_mz = 0.f;
    float s_mm = 0.f, s_bg = 0.f;
    float s_gtx = 0.f, s_gty = 0.f, s_gtz = 0.f;

    // Persistent grid-stride over independent (b,d,h) row tasks.
    // Interleaved order => h+1 / d+1 reloads are L1/L2 hits (neighbor
    // tasks run concurrently). Clamped neighbors self-zero the grad/TV
    // terms, so validity factors apply only to the mask counts.
    for (int task = gwarp; task < NTASKS; task += TOTW) {
        const int h = task & (HH - 1);
        const int d = (task >> 7) & (DD - 1);
        const int b = task >> 14;

        const int dskip = (d < DD - 1) ? HH * ROWQ : 0;
        const int hskip = (h < HH - 1) ? ROWQ : 0;

        const int mo = task * ROWQ + lane;
        const int po = mo + b * (CC - 1) * CSTR;

        const float4 m  = mask[mo];
        const float4 md = mask[mo + dskip];
        const float4 mh = mask[mo + hskip];

        const float4 mx4 = make_float4(fminf(m.x, md.x), fminf(m.y, md.y),
                                       fminf(m.z, md.z), fminf(m.w, md.w));
        const float4 my4 = make_float4(fminf(m.x, mh.x), fminf(m.y, mh.y),
                                       fminf(m.z, mh.z), fminf(m.w, mh.w));
        const float mnx = __shfl_down_sync(0xffffffffu, m.x, 1);
        const float mz0 = fminf(m.x, m.y), mz1 = fminf(m.y, m.z);
        const float mz2 = fminf(m.z, m.w), mz3 = fminf(m.w, mnx) * ze;

        {   // mask counts (validity factors only here; terms self-zero)
            const float dv = (d < DD - 1) ? 1.0f : 0.0f;
            const float hv = (h < HH - 1) ? 1.0f : 0.0f;
            s_m  += (m.x + m.y) + (m.z + m.w);
            s_mx += dv * ((mx4.x + mx4.y) + (mx4.z + mx4.w));
            s_my += hv * ((my4.x + my4.y) + (my4.z + my4.w));
            s_mz += (mz0 + mz1) + (mz2 + mz3);
        }

        // 1 - m, computed once, reused by all 3 channels
        const float4 inm = make_float4(1.f - m.x, 1.f - m.y,
                                       1.f - m.z, 1.f - m.w);

#pragma unroll
        for (int c = 0; c < CC; c++) {
            const float4 p  = pred[po + c * CSTR];
            const float4 t  = targ[po + c * CSTR];
            const float4 pd = pred[po + c * CSTR + dskip];
            const float4 td = targ[po + c * CSTR + dskip];
            const float4 ph = pred[po + c * CSTR + hskip];
            const float4 th = targ[po + c * CSTR + hskip];

            const float4 df  = make_float4(p.x - t.x, p.y - t.y,
                                           p.z - t.z, p.w - t.w);
            const float4 dfd = make_float4(pd.x - td.x, pd.y - td.y,
                                           pd.z - td.z, pd.w - td.w);
            const float4 dfh = make_float4(ph.x - th.x, ph.y - th.y,
                                           ph.z - th.z, ph.w - th.w);

            // (|diff| + diff^2) * m   (mae+mse share denominator)
            s_mm += fmaf(df.x, df.x, fabsf(df.x)) * m.x
                  + fmaf(df.y, df.y, fabsf(df.y)) * m.y
                  + fmaf(df.z, df.z, fabsf(df.z)) * m.z
                  + fmaf(df.w, df.w, fabsf(df.w)) * m.w;
            // |p| * (1 - m)
            s_bg += fabsf(p.x) * inm.x + fabsf(p.y) * inm.y
                  + fabsf(p.z) * inm.z + fabsf(p.w) * inm.w;

            // grad (0.1) + tv (0.002): shared denominators, weights folded
            s_gtx += fmaf(W_TV, fabsf(pd.x - p.x), W_GRAD * fabsf(dfd.x - df.x)) * mx4.x
                   + fmaf(W_TV, fabsf(pd.y - p.y), W_GRAD * fabsf(dfd.y - df.y)) * mx4.y
                   + fmaf(W_TV, fabsf(pd.z - p.z), W_GRAD * fabsf(dfd.z - df.z)) * mx4.z
                   + fmaf(W_TV, fabsf(pd.w - p.w), W_GRAD * fabsf(dfd.w - df.w)) * mx4.w;

            s_gty += fmaf(W_TV, fabsf(ph.x - p.x), W_GRAD * fabsf(dfh.x - df.x)) * my4.x
                   + fmaf(W_TV, fabsf(ph.y - p.y), W_GRAD * fabsf(dfh.y - df.y)) * my4.y
                   + fmaf(W_TV, fabsf(ph.z - p.z), W_GRAD * fabsf(dfh.z - df.z)) * my4.z
                   + fmaf(W_TV, fabsf(ph.w - p.w), W_GRAD * fabsf(dfh.w - df.w)) * my4.w;

            const float dnx = __shfl_down_sync(0xffffffffu, df.x, 1);
            const float pnx = __shfl_down_sync(0xffffffffu, p.x, 1);
            s_gtz += fmaf(W_TV, fabsf(p.y - p.x), W_GRAD * fabsf(df.y - df.x)) * mz0
                   + fmaf(W_TV, fabsf(p.z - p.y), W_GRAD * fabsf(df.z - df.y)) * mz1
                   + fmaf(W_TV, fabsf(p.w - p.z), W_GRAD * fabsf(df.w - df.z)) * mz2
                   + fmaf(W_TV, fabsf(pnx - p.w), W_GRAD * fabsf(dnx - df.w)) * mz3;
        }
    }

    // ---- block-level reduction: warp -> smem -> NSUMS atomics per block ----
    __shared__ float red[WPB][NSUMS];
    float vals[NSUMS] = {s_m, s_mx, s_my, s_mz, s_mm, s_bg,
                         s_gtx, s_gty, s_gtz};
#pragma unroll
    for (int i = 0; i < NSUMS; i++) {
        const float r = warp_sum(vals[i]);
        if (lane == 0) red[wid][i] = r;
    }
    __syncthreads();

    if (threadIdx.x < NSUMS) {
        float acc = red[0][threadIdx.x];
#pragma unroll
        for (int w = 1; w < WPB; w++) acc += red[w][threadIdx.x];
        atomicAdd(&g_sums[threadIdx.x], (double)acc);
        __threadfence();
    }
    __syncthreads();

    // ---- last block finalizes + resets scratch (graph-replay determinism) ----
    if (threadIdx.x == 0) {
        const unsigned int old = atomicAdd(&g_count, 1u);
        if (old == NBLOCKS - 1) {
            double s[NSUMS];
#pragma unroll
            for (int i = 0; i < NSUMS; i++) s[i] = atomicAdd(&g_sums[i], 0.0);
            const double e = 1e-8;
            const double sm  = s[0], smx = s[1], smy = s[2], smz = s[3];
            const double mm  = s[4], bg  = s[5];
            const double gtx = s[6], gty = s[7], gtz = s[8];
            const double inv = (double)BB * DD * HH * WW - sm;

            const double r = mm / (sm * 3.0 + e)          // mae + mse
                           + gtx / (smx * 3.0 + e)
                           + gty / (smy * 3.0 + e)
                           + gtz / (smz * 3.0 + e)
                           + W_BG * (bg / (inv * 3.0 + e));
            out[0] = (float)r;

#pragma unroll
            for (int i = 0; i < NSUMS; i++) g_sums[i] = 0.0;
            g_count = 0u;
        }
    }
}

extern "C" void kernel_launch(void* const* d_in, const int* in_sizes, int n_in,
                              void* d_out, int out_size) {
    // mask is the smallest input; pred/target keep their relative order
    int mi = 0;
    for (int i = 1; i < n_in; i++)
        if (in_sizes[i] < in_sizes[mi]) mi = i;
    int others[2], k = 0;
    for (int i = 0; i < 3; i++)
        if (i != mi) others[k++] = i;

    const float4* pred = (const float4*)d_in[others[0]];
    const float4* targ = (const float4*)d_in[others[1]];
    const float4* mask = (const float4*)d_in[mi];

    loss_kernel<<<NBLOCKS, NTHREADS>>>(pred, targ, mask, (float*)d_out);
}

// round 14
// speedup vs baseline: 1.3746x; 1.0279x over previous
#include <cuda_runtime.h>

#define BB 2
#define CC 3
#define DD 128
#define HH 128
#define WW 128
#define NTASKS (BB * DD * HH)        // 32768 row tasks (b,d,h)
#define NTHREADS 128
#define WPB (NTHREADS / 32)          // 4 warps/block
#define NBLOCKS (148 * 7)            // persistent: exactly 7 blocks/SM
#define TOTW (NBLOCKS * WPB)         // 4144 resident warps

#define W_GRAD 0.1f
#define W_TV 0.002f
#define W_BG 0.15

// 10 partial sums:
// 0:mask 1:mx 2:my 3:mz 4:(mae+mse) 5:|p| 6:|p|*m 7:gtx 8:gty 9:gtz
#define NSUMS 10
__device__ double g_sums[NSUMS];
__device__ unsigned int g_count;

__device__ __forceinline__ float warp_sum(float v) {
#pragma unroll
    for (int o = 16; o; o >>= 1) v += __shfl_down_sync(0xffffffffu, v, o);
    return v;
}

__global__ __launch_bounds__(NTHREADS, 7)   // 72-reg natural fit, no spills
void loss_kernel(const float4* __restrict__ pred,
                 const float4* __restrict__ targ,
                 const float4* __restrict__ mask,
                 float* __restrict__ out) {
    const int wid   = threadIdx.x >> 5;
    const int lane  = threadIdx.x & 31;
    const int gwarp = blockIdx.x * WPB + wid;

    const float ze = (lane < 31) ? 1.0f : 0.0f;       // w=127 edge
    const int ROWQ = WW / 4;                          // 32 float4 per row
    const int CSTR = DD * HH * ROWQ;                  // channel stride (float4)

    float s_m = 0.f, s_mx = 0.f, s_my = 0.f, s_mz = 0.f;
    float s_mm = 0.f, s_ba = 0.f, s_bm = 0.f;
    float s_gtx = 0.f, s_gty = 0.f, s_gtz = 0.f;

    // Persistent grid-stride over independent (b,d,h) row tasks.
    // Interleaved order => h+1 / d+1 reloads are L1/L2 hits (neighbor
    // tasks run concurrently). Clamped neighbors self-zero the grad/TV
    // terms, so validity factors apply only to the mask counts.
    for (int task = gwarp; task < NTASKS; task += TOTW) {
        const int h = task & (HH - 1);
        const int d = (task >> 7) & (DD - 1);
        const int b = task >> 14;

        const int dskip = (d < DD - 1) ? HH * ROWQ : 0;
        const int hskip = (h < HH - 1) ? ROWQ : 0;

        const int mo = task * ROWQ + lane;
        const int po = mo + b * (CC - 1) * CSTR;

        const float4 m  = mask[mo];
        const float4 md = mask[mo + dskip];
        const float4 mh = mask[mo + hskip];

        const float4 mx4 = make_float4(fminf(m.x, md.x), fminf(m.y, md.y),
                                       fminf(m.z, md.z), fminf(m.w, md.w));
        const float4 my4 = make_float4(fminf(m.x, mh.x), fminf(m.y, mh.y),
                                       fminf(m.z, mh.z), fminf(m.w, mh.w));
        const float mnx = __shfl_down_sync(0xffffffffu, m.x, 1);
        const float mz0 = fminf(m.x, m.y), mz1 = fminf(m.y, m.z);
        const float mz2 = fminf(m.z, m.w), mz3 = fminf(m.w, mnx) * ze;

        {   // mask counts (validity factors only here; terms self-zero)
            const float dv = (d < DD - 1) ? 1.0f : 0.0f;
            const float hv = (h < HH - 1) ? 1.0f : 0.0f;
            s_m  += (m.x + m.y) + (m.z + m.w);
            s_mx += dv * ((mx4.x + mx4.y) + (mx4.z + mx4.w));
            s_my += hv * ((my4.x + my4.y) + (my4.z + my4.w));
            s_mz += (mz0 + mz1) + (mz2 + mz3);
        }

#pragma unroll
        for (int c = 0; c < CC; c++) {
            const float4 p  = pred[po + c * CSTR];
            const float4 t  = targ[po + c * CSTR];
            const float4 pd = pred[po + c * CSTR + dskip];
            const float4 td = targ[po + c * CSTR + dskip];
            const float4 ph = pred[po + c * CSTR + hskip];
            const float4 th = targ[po + c * CSTR + hskip];

            // raw diffs — masking by min(m, m_nbr) makes products redundant
            const float4 df  = make_float4(p.x - t.x, p.y - t.y,
                                           p.z - t.z, p.w - t.w);
            const float4 dfd = make_float4(pd.x - td.x, pd.y - td.y,
                                           pd.z - td.z, pd.w - td.w);
            const float4 dfh = make_float4(ph.x - th.x, ph.y - th.y,
                                           ph.z - th.z, ph.w - th.w);

            // (|diff| + diff^2) * m  (mae+mse share denominator)
            s_mm += fmaf(df.x, df.x, fabsf(df.x)) * m.x
                  + fmaf(df.y, df.y, fabsf(df.y)) * m.y
                  + fmaf(df.z, df.z, fabsf(df.z)) * m.z
                  + fmaf(df.w, df.w, fabsf(df.w)) * m.w;
            // |p|*(1-m) = sum|p| - sum|p|*m
            const float ax = fabsf(p.x), ay = fabsf(p.y),
                        az = fabsf(p.z), aw = fabsf(p.w);
            s_ba += (ax + ay) + (az + aw);
            s_bm += ax * m.x + ay * m.y + az * m.z + aw * m.w;

            // grad (0.1) + tv (0.002): shared denominators, weights folded
            s_gtx += fmaf(W_TV, fabsf(pd.x - p.x), W_GRAD * fabsf(dfd.x - df.x)) * mx4.x
                   + fmaf(W_TV, fabsf(pd.y - p.y), W_GRAD * fabsf(dfd.y - df.y)) * mx4.y
                   + fmaf(W_TV, fabsf(pd.z - p.z), W_GRAD * fabsf(dfd.z - df.z)) * mx4.z
                   + fmaf(W_TV, fabsf(pd.w - p.w), W_GRAD * fabsf(dfd.w - df.w)) * mx4.w;

            s_gty += fmaf(W_TV, fabsf(ph.x - p.x), W_GRAD * fabsf(dfh.x - df.x)) * my4.x
                   + fmaf(W_TV, fabsf(ph.y - p.y), W_GRAD * fabsf(dfh.y - df.y)) * my4.y
                   + fmaf(W_TV, fabsf(ph.z - p.z), W_GRAD * fabsf(dfh.z - df.z)) * my4.z
                   + fmaf(W_TV, fabsf(ph.w - p.w), W_GRAD * fabsf(dfh.w - df.w)) * my4.w;

            const float dnx = __shfl_down_sync(0xffffffffu, df.x, 1);
            const float pnx = __shfl_down_sync(0xffffffffu, p.x, 1);
            s_gtz += fmaf(W_TV, fabsf(p.y - p.x), W_GRAD * fabsf(df.y - df.x)) * mz0
                   + fmaf(W_TV, fabsf(p.z - p.y), W_GRAD * fabsf(df.z - df.y)) * mz1
                   + fmaf(W_TV, fabsf(p.w - p.z), W_GRAD * fabsf(df.w - df.z)) * mz2
                   + fmaf(W_TV, fabsf(pnx - p.w), W_GRAD * fabsf(dnx - df.w)) * mz3;
        }
    }

    // ---- block-level reduction: warp -> smem -> NSUMS atomics per block ----
    __shared__ float red[WPB][NSUMS];
    float vals[NSUMS] = {s_m, s_mx, s_my, s_mz, s_mm, s_ba, s_bm,
                         s_gtx, s_gty, s_gtz};
#pragma unroll
    for (int i = 0; i < NSUMS; i++) {
        const float r = warp_sum(vals[i]);
        if (lane == 0) red[wid][i] = r;
    }
    __syncthreads();

    if (threadIdx.x < NSUMS) {
        float acc = red[0][threadIdx.x];
#pragma unroll
        for (int w = 1; w < WPB; w++) acc += red[w][threadIdx.x];
        atomicAdd(&g_sums[threadIdx.x], (double)acc);
        __threadfence();
    }
    __syncthreads();

    // ---- last block finalizes + resets scratch (graph-replay determinism) ----
    if (threadIdx.x == 0) {
        const unsigned int old = atomicAdd(&g_count, 1u);
        if (old == NBLOCKS - 1) {
            double s[NSUMS];
#pragma unroll
            for (int i = 0; i < NSUMS; i++) s[i] = atomicAdd(&g_sums[i], 0.0);
            const double e = 1e-8;
            const double sm  = s[0], smx = s[1], smy = s[2], smz = s[3];
            const double mm  = s[4];
            const double bg  = s[5] - s[6];     // sum|p| - sum|p|*m
            const double gtx = s[7], gty = s[8], gtz = s[9];
            const double inv = (double)BB * DD * HH * WW - sm;

            const double r = mm / (sm * 3.0 + e)          // mae + mse
                           + gtx / (smx * 3.0 + e)
                           + gty / (smy * 3.0 + e)
                           + gtz / (smz * 3.0 + e)
                           + W_BG * (bg / (inv * 3.0 + e));
            out[0] = (float)r;

#pragma unroll
            for (int i = 0; i < NSUMS; i++) g_sums[i] = 0.0;
            g_count = 0u;
        }
    }
}

extern "C" void kernel_launch(void* const* d_in, const int* in_sizes, int n_in,
                              void* d_out, int out_size) {
    // mask is the smallest input; pred/target keep their relative order
    int mi = 0;
    for (int i = 1; i < n_in; i++)
        if (in_sizes[i] < in_sizes[mi]) mi = i;
    int others[2], k = 0;
    for (int i = 0; i < 3; i++)
        if (i != mi) others[k++] = i;

    const float4* pred = (const float4*)d_in[others[0]];
    const float4* targ = (const float4*)d_in[others[1]];
    const float4* mask = (const float4*)d_in[mi];

    loss_kernel<<<NBLOCKS, NTHREADS>>>(pred, targ, mask, (float*)d_out);
}

// round 15
// speedup vs baseline: 1.3760x; 1.0010x over previous
#include <cuda_runtime.h>

#define BB 2
#define CC 3
#define DD 128
#define HH 128
#define WW 128
#define NTASKS (BB * DD * HH)        // 32768 row tasks (b,d,h)
#define NTHREADS 128
#define WPB (NTHREADS / 32)          // 4 warps/block
#define NBLOCKS (148 * 7)            // persistent: exactly 7 blocks/SM
#define TOTW (NBLOCKS * WPB)         // 4144 resident warps

#define W_GRAD 0.1f
#define W_TV 0.002f
#define W_BG 0.15

// 10 partial sums:
// 0:mask 1:mx 2:my 3:mz 4:(mae+mse) 5:|p| 6:|p|*m 7:gtx 8:gty 9:gtz
#define NSUMS 10
__device__ double g_sums[NSUMS];
__device__ unsigned int g_count;

__device__ __forceinline__ float warp_sum(float v) {
#pragma unroll
    for (int o = 16; o; o >>= 1) v += __shfl_down_sync(0xffffffffu, v, o);
    return v;
}

__device__ __forceinline__ void pf_l2(const void* p) {
    asm volatile("prefetch.global.L2 [%0];" :: "l"(p));
}

__global__ __launch_bounds__(NTHREADS, 7)   // 72-reg natural fit, no spills
void loss_kernel(const float4* __restrict__ pred,
                 const float4* __restrict__ targ,
                 const float4* __restrict__ mask,
                 float* __restrict__ out) {
    const int wid   = threadIdx.x >> 5;
    const int lane  = threadIdx.x & 31;
    const int gwarp = blockIdx.x * WPB + wid;

    const float ze = (lane < 31) ? 1.0f : 0.0f;       // w=127 edge
    const int ROWQ = WW / 4;                          // 32 float4 per row
    const int CSTR = DD * HH * ROWQ;                  // channel stride (float4)
    const int PFO  = TOTW * ROWQ;                     // next-task offset (float4)

    float s_m = 0.f, s_mx = 0.f, s_my = 0.f, s_mz = 0.f;
    float s_mm = 0.f, s_ba = 0.f, s_bm = 0.f;
    float s_gtx = 0.f, s_gty = 0.f, s_gtz = 0.f;

    // Persistent grid-stride over independent (b,d,h) row tasks.
    // Interleaved order => h+1 / d+1 reloads are L1/L2 hits (neighbor
    // tasks run concurrently). Clamped neighbors self-zero the grad/TV
    // terms, so validity factors apply only to the mask counts.
    // L2 prefetch of the NEXT task's self rows hides compulsory DRAM
    // latency (prefetch distance ~1 task >> 577-cyc DRAM latency).
    for (int task = gwarp; task < NTASKS; task += TOTW) {
        const int h = task & (HH - 1);
        const int d = (task >> 7) & (DD - 1);
        const int b = task >> 14;

        const int dskip = (d < DD - 1) ? HH * ROWQ : 0;
        const int hskip = (h < HH - 1) ? ROWQ : 0;

        const int mo = task * ROWQ + lane;
        const int po = mo + b * (CC - 1) * CSTR;

        // ---- prefetch next task's compulsory rows into L2 (no dest regs).
        // Stale b on a batch wrap only mis-prefetches; addresses remain
        // in-bounds: po + PFO + 2*CSTR <= 6*CSTR when task+TOTW < NTASKS.
        if (task + TOTW < NTASKS) {
            pf_l2(mask + mo + PFO);
#pragma unroll
            for (int c = 0; c < CC; c++) {
                pf_l2(pred + po + PFO + c * CSTR);
                pf_l2(targ + po + PFO + c * CSTR);
            }
        }

        const float4 m  = mask[mo];
        const float4 md = mask[mo + dskip];
        const float4 mh = mask[mo + hskip];

        const float4 mx4 = make_float4(fminf(m.x, md.x), fminf(m.y, md.y),
                                       fminf(m.z, md.z), fminf(m.w, md.w));
        const float4 my4 = make_float4(fminf(m.x, mh.x), fminf(m.y, mh.y),
                                       fminf(m.z, mh.z), fminf(m.w, mh.w));
        const float mnx = __shfl_down_sync(0xffffffffu, m.x, 1);
        const float mz0 = fminf(m.x, m.y), mz1 = fminf(m.y, m.z);
        const float mz2 = fminf(m.z, m.w), mz3 = fminf(m.w, mnx) * ze;

        {   // mask counts (validity factors only here; terms self-zero)
            const float dv = (d < DD - 1) ? 1.0f : 0.0f;
            const float hv = (h < HH - 1) ? 1.0f : 0.0f;
            s_m  += (m.x + m.y) + (m.z + m.w);
            s_mx += dv * ((mx4.x + mx4.y) + (mx4.z + mx4.w));
            s_my += hv * ((my4.x + my4.y) + (my4.z + my4.w));
            s_mz += (mz0 + mz1) + (mz2 + mz3);
        }

#pragma unroll
        for (int c = 0; c < CC; c++) {
            const float4 p  = pred[po + c * CSTR];
            const float4 t  = targ[po + c * CSTR];
            const float4 pd = pred[po + c * CSTR + dskip];
            const float4 td = targ[po + c * CSTR + dskip];
            const float4 ph = pred[po + c * CSTR + hskip];
            const float4 th = targ[po + c * CSTR + hskip];

            // raw diffs — masking by min(m, m_nbr) makes products redundant
            const float4 df  = make_float4(p.x - t.x, p.y - t.y,
                                           p.z - t.z, p.w - t.w);
            const float4 dfd = make_float4(pd.x - td.x, pd.y - td.y,
                                           pd.z - td.z, pd.w - td.w);
            const float4 dfh = make_float4(ph.x - th.x, ph.y - th.y,
                                           ph.z - th.z, ph.w - th.w);

            // (|diff| + diff^2) * m  (mae+mse share denominator)
            s_mm += fmaf(df.x, df.x, fabsf(df.x)) * m.x
                  + fmaf(df.y, df.y, fabsf(df.y)) * m.y
                  + fmaf(df.z, df.z, fabsf(df.z)) * m.z
                  + fmaf(df.w, df.w, fabsf(df.w)) * m.w;
            // |p|*(1-m) = sum|p| - sum|p|*m
            const float ax = fabsf(p.x), ay = fabsf(p.y),
                        az = fabsf(p.z), aw = fabsf(p.w);
            s_ba += (ax + ay) + (az + aw);
            s_bm += ax * m.x + ay * m.y + az * m.z + aw * m.w;

            // grad (0.1) + tv (0.002): shared denominators, weights folded
            s_gtx += fmaf(W_TV, fabsf(pd.x - p.x), W_GRAD * fabsf(dfd.x - df.x)) * mx4.x
                   + fmaf(W_TV, fabsf(pd.y - p.y), W_GRAD * fabsf(dfd.y - df.y)) * mx4.y
                   + fmaf(W_TV, fabsf(pd.z - p.z), W_GRAD * fabsf(dfd.z - df.z)) * mx4.z
                   + fmaf(W_TV, fabsf(pd.w - p.w), W_GRAD * fabsf(dfd.w - df.w)) * mx4.w;

            s_gty += fmaf(W_TV, fabsf(ph.x - p.x), W_GRAD * fabsf(dfh.x - df.x)) * my4.x
                   + fmaf(W_TV, fabsf(ph.y - p.y), W_GRAD * fabsf(dfh.y - df.y)) * my4.y
                   + fmaf(W_TV, fabsf(ph.z - p.z), W_GRAD * fabsf(dfh.z - df.z)) * my4.z
                   + fmaf(W_TV, fabsf(ph.w - p.w), W_GRAD * fabsf(dfh.w - df.w)) * my4.w;

            const float dnx = __shfl_down_sync(0xffffffffu, df.x, 1);
            const float pnx = __shfl_down_sync(0xffffffffu, p.x, 1);
            s_gtz += fmaf(W_TV, fabsf(p.y - p.x), W_GRAD * fabsf(df.y - df.x)) * mz0
                   + fmaf(W_TV, fabsf(p.z - p.y), W_GRAD * fabsf(df.z - df.y)) * mz1
                   + fmaf(W_TV, fabsf(p.w - p.z), W_GRAD * fabsf(df.w - df.z)) * mz2
                   + fmaf(W_TV, fabsf(pnx - p.w), W_GRAD * fabsf(dnx - df.w)) * mz3;
        }
    }

    // ---- block-level reduction: warp -> smem -> NSUMS atomics per block ----
    __shared__ float red[WPB][NSUMS];
    float vals[NSUMS] = {s_m, s_mx, s_my, s_mz, s_mm, s_ba, s_bm,
                         s_gtx, s_gty, s_gtz};
#pragma unroll
    for (int i = 0; i < NSUMS; i++) {
        const float r = warp_sum(vals[i]);
        if (lane == 0) red[wid][i] = r;
    }
    __syncthreads();

    if (threadIdx.x < NSUMS) {
        float acc = red[0][threadIdx.x];
#pragma unroll
        for (int w = 1; w < WPB; w++) acc += red[w][threadIdx.x];
        atomicAdd(&g_sums[threadIdx.x], (double)acc);
        __threadfence();
    }
    __syncthreads();

    // ---- last block finalizes + resets scratch (graph-replay determinism) ----
    if (threadIdx.x == 0) {
        const unsigned int old = atomicAdd(&g_count, 1u);
        if (old == NBLOCKS - 1) {
            double s[NSUMS];
#pragma unroll
            for (int i = 0; i < NSUMS; i++) s[i] = atomicAdd(&g_sums[i], 0.0);
            const double e = 1e-8;
            const double sm  = s[0], smx = s[1], smy = s[2], smz = s[3];
            const double mm  = s[4];
            const double bg  = s[5] - s[6];     // sum|p| - sum|p|*m
            const double gtx = s[7], gty = s[8], gtz = s[9];
            const double inv = (double)BB * DD * HH * WW - sm;

            const double r = mm / (sm * 3.0 + e)          // mae + mse
                           + gtx / (smx * 3.0 + e)
                           + gty / (smy * 3.0 + e)
                           + gtz / (smz * 3.0 + e)
                           + W_BG * (bg / (inv * 3.0 + e));
            out[0] = (float)r;

#pragma unroll
            for (int i = 0; i < NSUMS; i++) g_sums[i] = 0.0;
            g_count = 0u;
        }
    }
}

extern "C" void kernel_launch(void* const* d_in, const int* in_sizes, int n_in,
                              void* d_out, int out_size) {
    // mask is the smallest input; pred/target keep their relative order
    int mi = 0;
    for (int i = 1; i < n_in; i++)
        if (in_sizes[i] < in_sizes[mi]) mi = i;
    int others[2], k = 0;
    for (int i = 0; i < 3; i++)
        if (i != mi) others[k++] = i;

    const float4* pred = (const float4*)d_in[others[0]];
    const float4* targ = (const float4*)d_in[others[1]];
    const float4* mask = (const float4*)d_in[mi];

    loss_kernel<<<NBLOCKS, NTHREADS>>>(pred, targ, mask, (float*)d_out);
}